// round 15
// baseline (speedup 1.0000x reference)
#include <cuda_runtime.h>

// y[..., 2k]   = T[k,0,0]*x[2k] + T[k,0,1]*x[2k+1]
// y[..., 2k+1] = T[k,1,0]*x[2k] + T[k,1,1]*x[2k+1]
// x: (8192 rows, 4096 floats) fp32, twiddle: (2048, 2, 2) fp32 (32 KiB).
//
// FINAL converged configuration (session-best kernel 35.87us, DRAM 75.3% =
// mixed-R/W HBM floor; best harness 43.52us):
//  - 128-thread blocks, each owning a quarter-row column slice of 4 rows
//    -> grid 8192
//  - twiddle loaded FIRST (L1/L2-fast, scoreboard frees early), pinned
//    with evict_last, reused 4x from registers
//  - 4 front-batched independent streaming LDG.256 (deep MLP), STG.256
//    with evict_first so the write stream stays out of L2's way

struct f8 { float v[8]; };

__device__ __forceinline__ f8 ldg256_stream(const float* p) {
    f8 r;
    asm volatile("ld.global.nc.L2::evict_first.v8.b32 "
                 "{%0,%1,%2,%3,%4,%5,%6,%7}, [%8];"
                 : "=f"(r.v[0]), "=f"(r.v[1]), "=f"(r.v[2]), "=f"(r.v[3]),
                   "=f"(r.v[4]), "=f"(r.v[5]), "=f"(r.v[6]), "=f"(r.v[7])
                 : "l"(p));
    return r;
}

__device__ __forceinline__ f8 ldg256_pin(const float* p) {
    f8 r;
    asm volatile("ld.global.nc.L2::evict_last.v8.b32 "
                 "{%0,%1,%2,%3,%4,%5,%6,%7}, [%8];"
                 : "=f"(r.v[0]), "=f"(r.v[1]), "=f"(r.v[2]), "=f"(r.v[3]),
                   "=f"(r.v[4]), "=f"(r.v[5]), "=f"(r.v[6]), "=f"(r.v[7])
                 : "l"(p));
    return r;
}

__device__ __forceinline__ void stg256_stream(float* p, const f8& r) {
    asm volatile("st.global.L2::evict_first.v8.b32 "
                 "[%0], {%1,%2,%3,%4,%5,%6,%7,%8};"
                 :: "l"(p),
                    "f"(r.v[0]), "f"(r.v[1]), "f"(r.v[2]), "f"(r.v[3]),
                    "f"(r.v[4]), "f"(r.v[5]), "f"(r.v[6]), "f"(r.v[7])
                 : "memory");
}

static constexpr int ROW_FLOATS     = 4096;
static constexpr int ROWS_PER_BLOCK = 4;
static constexpr int BLOCK_THREADS  = 128;

__global__ __launch_bounds__(BLOCK_THREADS) void butterfly_kernel(
    const float* __restrict__ x,
    const float* __restrict__ tw,
    float* __restrict__ y)
{
    // blockIdx.x = row_group * 4 + quarter; 2048 row groups of 4 rows,
    // 4 quarter-row column slices (128 chunks of 8 floats each).
    const int quarter = blockIdx.x & 3;
    const int grp     = blockIdx.x >> 2;
    const int chunk   = (quarter << 7) + threadIdx.x;  // 0..511
    const int col     = chunk << 3;

    // Twiddle first: hits L1/L2 fast, frees its scoreboard slots early.
    const f8 ta = ldg256_pin(&tw[chunk << 4]);
    const f8 tb = ldg256_pin(&tw[(chunk << 4) + 8]);

    const long base = (long)grp * ROWS_PER_BLOCK * ROW_FLOATS + col;

    f8 v[ROWS_PER_BLOCK];
    // 4 independent streaming 256-bit loads: the only long-latency waits.
#pragma unroll
    for (int u = 0; u < ROWS_PER_BLOCK; u++)
        v[u] = ldg256_stream(&x[base + (long)u * ROW_FLOATS]);

#pragma unroll
    for (int u = 0; u < ROWS_PER_BLOCK; u++) {
        f8 o;
        o.v[0] = fmaf(ta.v[0], v[u].v[0], ta.v[1] * v[u].v[1]);
        o.v[1] = fmaf(ta.v[2], v[u].v[0], ta.v[3] * v[u].v[1]);
        o.v[2] = fmaf(ta.v[4], v[u].v[2], ta.v[5] * v[u].v[3]);
        o.v[3] = fmaf(ta.v[6], v[u].v[2], ta.v[7] * v[u].v[3]);
        o.v[4] = fmaf(tb.v[0], v[u].v[4], tb.v[1] * v[u].v[5]);
        o.v[5] = fmaf(tb.v[2], v[u].v[4], tb.v[3] * v[u].v[5]);
        o.v[6] = fmaf(tb.v[4], v[u].v[6], tb.v[5] * v[u].v[7]);
        o.v[7] = fmaf(tb.v[6], v[u].v[6], tb.v[7] * v[u].v[7]);
        stg256_stream(&y[base + (long)u * ROW_FLOATS], o);
    }
}

extern "C" void kernel_launch(void* const* d_in, const int* in_sizes, int n_in,
                              void* d_out, int out_size)
{
    const float* x  = (const float*)d_in[0];
    const float* tw = (const float*)d_in[1];
    float* y        = (float*)d_out;

    const int rows   = out_size / ROW_FLOATS;            // 8192
    const int blocks = (rows / ROWS_PER_BLOCK) * 4;      // 8192

    butterfly_kernel<<<blocks, BLOCK_THREADS>>>(x, tw, y);
}

// round 16
// speedup vs baseline: 1.0360x; 1.0360x over previous
#include <cuda_runtime.h>

// y[..., 2k]   = T[k,0,0]*x[2k] + T[k,0,1]*x[2k+1]
// y[..., 2k+1] = T[k,1,0]*x[2k] + T[k,1,1]*x[2k+1]
// x: (8192 rows, 4096 floats) fp32, twiddle: (2048, 2, 2) fp32 (32 KiB).
//
// FINAL configuration (best measured: kernel 36.0us @ DRAM 75.2%, harness
// 43.52us twice with this shape):
//  - 256-thread blocks, each owning a half-row column slice of 4 rows
//    -> grid 4096
//  - twiddle loaded FIRST (L1/L2-fast, frees scoreboard early), pinned
//    with evict_last, reused 4x from registers
//  - 4 front-batched independent streaming LDG.256 (deep MLP), STG.256
//    evict_first so the write stream stays out of L2
// Kernel is at the mixed-R/W HBM floor; remaining wall-clock variance is
// harness noise (+-1.5us demonstrated on identical binaries).

struct f8 { float v[8]; };

__device__ __forceinline__ f8 ldg256_stream(const float* p) {
    f8 r;
    asm volatile("ld.global.nc.L2::evict_first.v8.b32 "
                 "{%0,%1,%2,%3,%4,%5,%6,%7}, [%8];"
                 : "=f"(r.v[0]), "=f"(r.v[1]), "=f"(r.v[2]), "=f"(r.v[3]),
                   "=f"(r.v[4]), "=f"(r.v[5]), "=f"(r.v[6]), "=f"(r.v[7])
                 : "l"(p));
    return r;
}

__device__ __forceinline__ f8 ldg256_pin(const float* p) {
    f8 r;
    asm volatile("ld.global.nc.L2::evict_last.v8.b32 "
                 "{%0,%1,%2,%3,%4,%5,%6,%7}, [%8];"
                 : "=f"(r.v[0]), "=f"(r.v[1]), "=f"(r.v[2]), "=f"(r.v[3]),
                   "=f"(r.v[4]), "=f"(r.v[5]), "=f"(r.v[6]), "=f"(r.v[7])
                 : "l"(p));
    return r;
}

__device__ __forceinline__ void stg256_stream(float* p, const f8& r) {
    asm volatile("st.global.L2::evict_first.v8.b32 "
                 "[%0], {%1,%2,%3,%4,%5,%6,%7,%8};"
                 :: "l"(p),
                    "f"(r.v[0]), "f"(r.v[1]), "f"(r.v[2]), "f"(r.v[3]),
                    "f"(r.v[4]), "f"(r.v[5]), "f"(r.v[6]), "f"(r.v[7])
                 : "memory");
}

static constexpr int ROW_FLOATS     = 4096;
static constexpr int ROWS_PER_BLOCK = 4;
static constexpr int BLOCK_THREADS  = 256;

__global__ __launch_bounds__(BLOCK_THREADS) void butterfly_kernel(
    const float* __restrict__ x,
    const float* __restrict__ tw,
    float* __restrict__ y)
{
    // blockIdx.x = row_group * 2 + column_half; 2048 row groups of 4 rows.
    const int half  = blockIdx.x & 1;
    const int grp   = blockIdx.x >> 1;
    const int chunk = (half << 8) + threadIdx.x;   // 0..511, 8 floats each
    const int col   = chunk << 3;

    // Twiddle first: hits L1/L2 fast, frees its scoreboard slots early.
    const f8 ta = ldg256_pin(&tw[chunk << 4]);
    const f8 tb = ldg256_pin(&tw[(chunk << 4) + 8]);

    const float* xp = x + (long)grp * ROWS_PER_BLOCK * ROW_FLOATS + col;
    float*       yp = y + (long)grp * ROWS_PER_BLOCK * ROW_FLOATS + col;

    f8 v[ROWS_PER_BLOCK];
    // 4 independent streaming 256-bit loads: the only long-latency waits.
#pragma unroll
    for (int u = 0; u < ROWS_PER_BLOCK; u++)
        v[u] = ldg256_stream(xp + (long)u * ROW_FLOATS);

#pragma unroll
    for (int u = 0; u < ROWS_PER_BLOCK; u++) {
        f8 o;
        o.v[0] = fmaf(ta.v[0], v[u].v[0], ta.v[1] * v[u].v[1]);
        o.v[1] = fmaf(ta.v[2], v[u].v[0], ta.v[3] * v[u].v[1]);
        o.v[2] = fmaf(ta.v[4], v[u].v[2], ta.v[5] * v[u].v[3]);
        o.v[3] = fmaf(ta.v[6], v[u].v[2], ta.v[7] * v[u].v[3]);
        o.v[4] = fmaf(tb.v[0], v[u].v[4], tb.v[1] * v[u].v[5]);
        o.v[5] = fmaf(tb.v[2], v[u].v[4], tb.v[3] * v[u].v[5]);
        o.v[6] = fmaf(tb.v[4], v[u].v[6], tb.v[5] * v[u].v[7]);
        o.v[7] = fmaf(tb.v[6], v[u].v[6], tb.v[7] * v[u].v[7]);
        stg256_stream(yp + (long)u * ROW_FLOATS, o);
    }
}

extern "C" void kernel_launch(void* const* d_in, const int* in_sizes, int n_in,
                              void* d_out, int out_size)
{
    const float* x  = (const float*)d_in[0];
    const float* tw = (const float*)d_in[1];
    float* y        = (float*)d_out;

    const int rows   = out_size / ROW_FLOATS;            // 8192
    const int blocks = (rows / ROWS_PER_BLOCK) * 2;      // 4096

    butterfly_kernel<<<blocks, BLOCK_THREADS>>>(x, tw, y);
}